// round 1
// baseline (speedup 1.0000x reference)
#include <cuda_runtime.h>
#include <math.h>

// Scratch (no allocations allowed): per-ROI level and output position.
#define MAXR 8192
__device__ int g_level[MAXR];
__device__ int g_pos[MAXR];

// ---------------------------------------------------------------------------
// Kernel 1: per-ROI FPN level
// spec = log2( sqrt(max(h*w,1e-12)) / (224 / sqrt(image_h*image_w)) )
// level = clip(4 + round(spec), 2, 5)   (round = half-to-even, like jnp.round)
// ---------------------------------------------------------------------------
__global__ void k_levels(const float* __restrict__ rois,
                         const int* __restrict__ ih, const int* __restrict__ iw,
                         int R)
{
    int r = blockIdx.x * blockDim.x + threadIdx.x;
    if (r >= R) return;
    float y1 = rois[4 * r + 0];
    float x1 = rois[4 * r + 1];
    float y2 = rois[4 * r + 2];
    float x2 = rois[4 * r + 3];
    float h = y2 - y1;
    float w = x2 - x1;
    float area  = (float)((*ih) * (*iw));
    float canon = 224.0f / sqrtf(area);
    float spec  = log2f(sqrtf(fmaxf(h * w, 1e-12f)) / canon);
    int lvl = 4 + (int)rintf(spec);
    lvl = lvl < 2 ? 2 : (lvl > 5 ? 5 : lvl);
    g_level[r] = lvl;
}

// ---------------------------------------------------------------------------
// Kernel 2: stable-sort rank.  pos[r] = #{j: lvl[j]<lvl[r]} + #{j<r: lvl[j]==lvl[r]}
// O(R^2) but R=2000 -> 4M shared-mem compares spread over ceil(R/128) blocks.
// ---------------------------------------------------------------------------
__global__ void k_pos(int R)
{
    __shared__ int slv[MAXR];
    for (int j = threadIdx.x; j < R; j += blockDim.x) slv[j] = g_level[j];
    __syncthreads();
    int r = blockIdx.x * blockDim.x + threadIdx.x;
    if (r >= R) return;
    int myl = slv[r];
    int pos = 0;
    for (int j = 0; j < R; ++j) {
        int lj = slv[j];
        pos += (int)((lj < myl) | ((lj == myl) & (j < r)));
    }
    g_pos[r] = pos;
}

// ---------------------------------------------------------------------------
// Kernel 3: bilinear crop-and-resize gather.
// One 64-thread block per (roi, py, px); thread t handles channels 4t..4t+3
// via float4 (fully coalesced: each tap is a contiguous 1KB NHWC row segment).
// ---------------------------------------------------------------------------
__global__ void k_roialign(const float* __restrict__ rois,
                           const float* __restrict__ p2,
                           const float* __restrict__ p3,
                           const float* __restrict__ p4,
                           const float* __restrict__ p5,
                           float* __restrict__ out,
                           int R, int N, int C)
{
    int blk  = blockIdx.x;
    int r    = blk / 49;
    int cell = blk - r * 49;
    int py   = cell / 7;
    int px   = cell - py * 7;
    int lane = threadIdx.x;            // 0 .. C/4-1

    float y1 = __ldg(&rois[4 * r + 0]);
    float x1 = __ldg(&rois[4 * r + 1]);
    float y2 = __ldg(&rois[4 * r + 2]);
    float x2 = __ldg(&rois[4 * r + 3]);

    int lvl = g_level[r];
    int pos = g_pos[r];
    int b   = r / N;

    const float* feat;
    int H;
    switch (lvl) {
        case 2:  feat = p2; H = 256; break;
        case 3:  feat = p3; H = 128; break;
        case 4:  feat = p4; H = 64;  break;
        default: feat = p5; H = 32;  break;
    }
    int W = H;

    float fy = (float)py / 6.0f;
    float fx = (float)px / 6.0f;
    float in_y = (y1 + fy * (y2 - y1)) * (float)(H - 1);
    float in_x = (x1 + fx * (x2 - x1)) * (float)(W - 1);

    float y0f = floorf(in_y);
    float x0f = floorf(in_x);
    float wy = in_y - y0f;
    float wx = in_x - x0f;
    int y0 = (int)y0f;
    int x0 = (int)x0f;
    int y0c = min(max(y0,     0), H - 1);
    int y1c = min(max(y0 + 1, 0), H - 1);
    int x0c = min(max(x0,     0), W - 1);
    int x1c = min(max(x0 + 1, 0), W - 1);

    bool valid = (in_y >= 0.0f) && (in_y <= (float)(H - 1)) &&
                 (in_x >= 0.0f) && (in_x <= (float)(W - 1));
    float vm = valid ? 1.0f : 0.0f;

    int base = b * H * W;            // <= 2*256*256, fits int easily
    const float4* f00 = (const float4*)(feat + (long long)(base + y0c * W + x0c) * C);
    const float4* f01 = (const float4*)(feat + (long long)(base + y0c * W + x1c) * C);
    const float4* f10 = (const float4*)(feat + (long long)(base + y1c * W + x0c) * C);
    const float4* f11 = (const float4*)(feat + (long long)(base + y1c * W + x1c) * C);

    float4 v00 = __ldg(&f00[lane]);
    float4 v01 = __ldg(&f01[lane]);
    float4 v10 = __ldg(&f10[lane]);
    float4 v11 = __ldg(&f11[lane]);

    float owx = 1.0f - wx;
    float owy = 1.0f - wy;

    float4 res;
    res.x = ((v00.x * owx + v01.x * wx) * owy + (v10.x * owx + v11.x * wx) * wy) * vm;
    res.y = ((v00.y * owx + v01.y * wx) * owy + (v10.y * owx + v11.y * wx) * wy) * vm;
    res.z = ((v00.z * owx + v01.z * wx) * owy + (v10.z * owx + v11.z * wx) * wy) * vm;
    res.w = ((v00.w * owx + v01.w * wx) * owy + (v10.w * owx + v11.w * wx) * wy) * vm;

    float4* o = (float4*)(out + (long long)(pos * 49 + cell) * C);
    o[lane] = res;
}

// ---------------------------------------------------------------------------
// Inputs (metadata order): rois [B*N*4] f32, image_h [1] i32, image_w [1] i32,
//                          p2, p3, p4, p5 (NHWC f32). Output: [R,7,7,C] f32.
// ---------------------------------------------------------------------------
extern "C" void kernel_launch(void* const* d_in, const int* in_sizes, int n_in,
                              void* d_out, int out_size)
{
    const float* rois = (const float*)d_in[0];
    const int*   ih   = (const int*)d_in[1];
    const int*   iw   = (const int*)d_in[2];
    const float* p2   = (const float*)d_in[3];
    const float* p3   = (const float*)d_in[4];
    const float* p4   = (const float*)d_in[5];
    const float* p5   = (const float*)d_in[6];
    float* out = (float*)d_out;

    int R = in_sizes[0] / 4;
    int C = 256;
    int B = in_sizes[3] / (256 * 256 * C);   // p2 is [B,256,256,256]
    if (B < 1) B = 1;
    int N = R / B;

    int threads = 128;
    int blocks  = (R + threads - 1) / threads;
    k_levels<<<blocks, threads>>>(rois, ih, iw, R);
    k_pos<<<blocks, threads>>>(R);
    k_roialign<<<R * 49, C / 4>>>(rois, p2, p3, p4, p5, out, R, N, C);
}